// round 1
// baseline (speedup 1.0000x reference)
#include <cuda_runtime.h>
#include <math.h>

#define BATCH 16
#define NCLS  20
#define NSEL  2400
#define KTOP  100
#define NPRE  1000

// ---------------- scratch (device globals; no allocations allowed) ----------
__device__ float  g_ml0[BATCH * 6400];
__device__ float  g_ml1[BATCH * 1600];
__device__ int    g_sel[BATCH * 2 * NPRE];
__device__ float4 g_boxes[BATCH * NSEL];
__device__ float  g_scoresT[BATCH * NCLS * NSEL];   // [b][c][s]
__device__ float  g_selscore[BATCH * NCLS * KTOP];
__device__ int    g_selidx[BATCH * NCLS * KTOP];

__device__ __forceinline__ unsigned f2u(float f) {
    unsigned u = __float_as_uint(f);
    return (u & 0x80000000u) ? ~u : (u | 0x80000000u);
}
__device__ __forceinline__ unsigned long long umax64(unsigned long long a, unsigned long long b) {
    return a > b ? a : b;
}

// ---------------- K1: max class logit per anchor (levels 0,1) ---------------
__global__ void k_maxlogit(const float* __restrict__ cls0, const float* __restrict__ cls1) {
    int gid = blockIdx.x * blockDim.x + threadIdx.x;
    const int n0 = BATCH * 6400;
    if (gid < n0) {
        const float* p = cls0 + (size_t)gid * NCLS;
        float m = p[0];
        #pragma unroll
        for (int i = 1; i < NCLS; i++) m = fmaxf(m, p[i]);
        g_ml0[gid] = m;
    } else {
        int g1 = gid - n0;
        if (g1 < BATCH * 1600) {
            const float* p = cls1 + (size_t)g1 * NCLS;
            float m = p[0];
            #pragma unroll
            for (int i = 1; i < NCLS; i++) m = fmaxf(m, p[i]);
            g_ml1[g1] = m;
        }
    }
}

// ---------------- K2: radix-select top-1000 per (batch, level) --------------
__global__ void __launch_bounds__(256) k_select() {
    __shared__ unsigned su[6400];
    __shared__ int sred[8];
    __shared__ int sb;
    __shared__ int c1, c2;
    int b = blockIdx.x >> 1, l = blockIdx.x & 1;
    int n = l ? 1600 : 6400;
    const float* src = l ? (g_ml1 + b * 1600) : (g_ml0 + b * 6400);
    int t = threadIdx.x;
    for (int i = t; i < n; i += 256) su[i] = f2u(src[i]);
    if (t == 0) { c1 = 0; c2 = 0; }
    __syncthreads();

    unsigned v = 0;
    for (int bit = 31; bit >= 0; --bit) {
        unsigned cand = v | (1u << bit);
        int cnt = 0;
        for (int i = t; i < n; i += 256) cnt += (su[i] >= cand);
        #pragma unroll
        for (int o = 16; o; o >>= 1) cnt += __shfl_down_sync(0xffffffffu, cnt, o);
        if ((t & 31) == 0) sred[t >> 5] = cnt;
        __syncthreads();
        if (t == 0) { int s = 0; for (int w = 0; w < 8; w++) s += sred[w]; sb = s; }
        __syncthreads();
        if (sb >= NPRE) v = cand;
    }
    // strictly greater count
    {
        int cnt = 0;
        for (int i = t; i < n; i += 256) cnt += (su[i] > v);
        #pragma unroll
        for (int o = 16; o; o >>= 1) cnt += __shfl_down_sync(0xffffffffu, cnt, o);
        if ((t & 31) == 0) sred[t >> 5] = cnt;
        __syncthreads();
        if (t == 0) { int s = 0; for (int w = 0; w < 8; w++) s += sred[w]; sb = s; }
        __syncthreads();
    }
    int G = sb;
    int* out = g_sel + (b * 2 + l) * NPRE;
    for (int i = t; i < n; i += 256)
        if (su[i] > v) { int p = atomicAdd(&c1, 1); out[p] = i; }
    __syncthreads();
    for (int i = t; i < n; i += 256)
        if (su[i] == v) { int p = atomicAdd(&c2, 1); if (G + p < NPRE) out[G + p] = i; }
}

// ---------------- K3: gather survivors, compute scores + DFL boxes ----------
__global__ void k_gather(const float* __restrict__ cls0, const float* __restrict__ cls1,
                         const float* __restrict__ cls2,
                         const float* __restrict__ bb0, const float* __restrict__ bb1,
                         const float* __restrict__ bb2) {
    int gid = blockIdx.x * blockDim.x + threadIdx.x;
    if (gid >= BATCH * NSEL) return;
    int b = gid / NSEL, s = gid % NSEL;
    const float* cls; const float* bb; int anchor; int w; float stride;
    if (s < 1000) {
        anchor = g_sel[(b * 2 + 0) * NPRE + s]; w = 80; stride = 8.f;
        cls = cls0 + ((size_t)b * 6400 + anchor) * NCLS;
        bb  = bb0 + ((size_t)b * 6400 + anchor) * 32;
    } else if (s < 2000) {
        anchor = g_sel[(b * 2 + 1) * NPRE + (s - 1000)]; w = 40; stride = 16.f;
        cls = cls1 + ((size_t)b * 1600 + anchor) * NCLS;
        bb  = bb1 + ((size_t)b * 1600 + anchor) * 32;
    } else {
        anchor = s - 2000; w = 20; stride = 32.f;
        cls = cls2 + ((size_t)b * 400 + anchor) * NCLS;
        bb  = bb2 + ((size_t)b * 400 + anchor) * 32;
    }
    float py = ((float)(anchor / w) + 0.5f) * stride;
    float px = ((float)(anchor % w) + 0.5f) * stride;
    float d[4];
    #pragma unroll
    for (int g = 0; g < 4; g++) {
        float x[8]; float m = -INFINITY;
        #pragma unroll
        for (int k = 0; k < 8; k++) { x[k] = bb[g * 8 + k]; m = fmaxf(m, x[k]); }
        float den = 0.f, num = 0.f;
        #pragma unroll
        for (int k = 0; k < 8; k++) { float e = expf(x[k] - m); den += e; num += e * (float)k; }
        d[g] = num / den * stride;
    }
    float y1 = fminf(fmaxf(py - d[0], 0.f), 640.f);
    float x1 = fminf(fmaxf(px - d[1], 0.f), 640.f);
    float y2 = fminf(fmaxf(py + d[2], 0.f), 640.f);
    float x2 = fminf(fmaxf(px + d[3], 0.f), 640.f);
    g_boxes[b * NSEL + s] = make_float4(y1, x1, y2, x2);
    #pragma unroll
    for (int c = 0; c < NCLS; c++) {
        float sc = 1.f / (1.f + expf(-cls[c]));
        g_scoresT[((size_t)b * NCLS + c) * NSEL + s] = sc;
    }
}

// ---------------- K4: greedy NMS, one block per (batch, class) --------------
__global__ void __launch_bounds__(256) k_nms() {
    const int ITEMS = 10;  // 10*256 = 2560 >= 2400
    int b = blockIdx.x / NCLS, c = blockIdx.x % NCLS;
    int t = threadIdx.x;
    float y1[ITEMS], x1[ITEMS], y2[ITEMS], x2[ITEMS], sc[ITEMS];
    const float*  scores = g_scoresT + ((size_t)b * NCLS + c) * NSEL;
    const float4* boxes  = g_boxes + b * NSEL;
    #pragma unroll
    for (int j = 0; j < ITEMS; j++) {
        int idx = j * 256 + t;
        if (idx < NSEL) {
            float4 v = boxes[idx];
            y1[j] = v.x; x1[j] = v.y; y2[j] = v.z; x2[j] = v.w;
            sc[j] = scores[idx];
        } else { sc[j] = -INFINITY; y1[j] = x1[j] = y2[j] = x2[j] = 0.f; }
    }
    __shared__ unsigned long long wmax[8];
    __shared__ float4 sbox;
    float* selS = g_selscore + ((size_t)b * NCLS + c) * KTOP;
    int*   selI = g_selidx + ((size_t)b * NCLS + c) * KTOP;

    for (int it = 0; it < KTOP; ++it) {
        unsigned long long best = 0ull;
        #pragma unroll
        for (int j = 0; j < ITEMS; j++) {
            int idx = j * 256 + t;
            unsigned long long key =
                ((unsigned long long)f2u(sc[j]) << 32) | (unsigned)(2999 - idx);
            best = umax64(best, key);
        }
        #pragma unroll
        for (int o = 16; o; o >>= 1)
            best = umax64(best, __shfl_down_sync(0xffffffffu, best, o));
        if ((t & 31) == 0) wmax[t >> 5] = best;
        __syncthreads();
        unsigned long long bk = wmax[0];
        #pragma unroll
        for (int w2 = 1; w2 < 8; w2++) bk = umax64(bk, wmax[w2]);
        int bidx = 2999 - (int)(unsigned)(bk & 0xFFFFFFFFull);
        #pragma unroll
        for (int j = 0; j < ITEMS; j++) {
            if (j * 256 + t == bidx) {
                sbox = make_float4(y1[j], x1[j], y2[j], x2[j]);
                selS[it] = sc[j];
                selI[it] = bidx;
                sc[j] = -INFINITY;        // suppress self (s.at[i].set(-inf))
            }
        }
        __syncthreads();
        float4 bbx = sbox;
        float a1 = (bbx.z - bbx.x) * (bbx.w - bbx.y);
        #pragma unroll
        for (int j = 0; j < ITEMS; j++) {
            float yy1 = fmaxf(bbx.x, y1[j]);
            float xx1 = fmaxf(bbx.y, x1[j]);
            float yy2 = fminf(bbx.z, y2[j]);
            float xx2 = fminf(bbx.w, x2[j]);
            float inter = fmaxf(yy2 - yy1, 0.f) * fmaxf(xx2 - xx1, 0.f);
            float a2 = (y2[j] - y1[j]) * (x2[j] - x1[j]);
            float iou = inter / (a1 + a2 - inter + 1e-9f);
            if (iou > 0.5f) sc[j] = -INFINITY;
        }
    }
}

// ---------------- K5: per-batch bitonic top-100 + masking -------------------
__global__ void __launch_bounds__(1024) k_final(float* __restrict__ out) {
    __shared__ unsigned long long keys[2048];
    int b = blockIdx.x, t = threadIdx.x;
    for (int i = t; i < 2048; i += 1024) {
        unsigned long long key = 0ull;
        if (i < NCLS * KTOP) {
            float s = g_selscore[(size_t)b * NCLS * KTOP + i];
            float fs = isfinite(s) ? s : -1.0f;
            // descending score, then ascending flat index (class-major), like lax.top_k
            key = ((unsigned long long)f2u(fs) << 32) | (unsigned)(0xFFFFFFFFu - (unsigned)i);
        }
        keys[i] = key;
    }
    __syncthreads();
    for (int k = 2; k <= 2048; k <<= 1) {
        for (int j = k >> 1; j > 0; j >>= 1) {
            for (int i = t; i < 2048; i += 1024) {
                int ixj = i ^ j;
                if (ixj > i) {
                    bool desc = (i & k) == 0;
                    unsigned long long a = keys[i], bb2 = keys[ixj];
                    bool sw = desc ? (a < bb2) : (a > bb2);
                    if (sw) { keys[i] = bb2; keys[ixj] = a; }
                }
            }
            __syncthreads();
        }
    }
    if (t < KTOP) {
        unsigned long long key = keys[t];
        unsigned low = (unsigned)(key & 0xFFFFFFFFull);
        unsigned i = 0xFFFFFFFFu - low;
        float* o = out + ((size_t)b * KTOP + t) * 6;
        float vals[6] = {0.f, 0.f, 0.f, 0.f, 0.f, 0.f};
        if (i < (unsigned)(NCLS * KTOP)) {
            int c = (int)i / KTOP, kk = (int)i % KTOP;
            float s = g_selscore[((size_t)b * NCLS + c) * KTOP + kk];
            if (isfinite(s) && s > 0.3f) {   // ok-mask and score-mask combined
                int idx = g_selidx[((size_t)b * NCLS + c) * KTOP + kk];
                float4 bx = g_boxes[b * NSEL + idx];
                vals[0] = bx.x; vals[1] = bx.y; vals[2] = bx.z; vals[3] = bx.w;
                vals[4] = s; vals[5] = (float)c;
            }
        }
        #pragma unroll
        for (int q = 0; q < 6; q++) o[q] = vals[q];
    }
}

// ---------------- launch -----------------------------------------------------
extern "C" void kernel_launch(void* const* d_in, const int* in_sizes, int n_in,
                              void* d_out, int out_size) {
    const float *cls0 = 0, *cls1 = 0, *cls2 = 0, *bb0 = 0, *bb1 = 0, *bb2 = 0;
    for (int i = 0; i < n_in; i++) {
        const float* p = (const float*)d_in[i];
        switch (in_sizes[i]) {
            case 2048000: cls0 = p; break;  // 16*6400*20
            case 3276800: bb0  = p; break;  // 16*6400*32
            case 512000:  cls1 = p; break;  // 16*1600*20
            case 819200:  bb1  = p; break;  // 16*1600*32
            case 128000:  cls2 = p; break;  // 16*400*20
            case 204800:  bb2  = p; break;  // 16*400*32
            default: break;                 // origin_shapes (unused by reference)
        }
    }
    k_maxlogit<<<(BATCH * 8000 + 255) / 256, 256>>>(cls0, cls1);
    k_select<<<32, 256>>>();
    k_gather<<<(BATCH * NSEL + 255) / 256, 256>>>(cls0, cls1, cls2, bb0, bb1, bb2);
    k_nms<<<BATCH * NCLS, 256>>>();
    k_final<<<BATCH, 1024>>>((float*)d_out);
}

// round 2
// speedup vs baseline: 1.3599x; 1.3599x over previous
#include <cuda_runtime.h>
#include <math.h>

#define BATCH 16
#define NCLS  20
#define NSEL  2400
#define KTOP  100
#define NPRE  1000

// ---------------- scratch (device globals; no allocations allowed) ----------
__device__ float  g_ml0[BATCH * 6400];
__device__ float  g_ml1[BATCH * 1600];
__device__ int    g_sel[BATCH * 2 * NPRE];
__device__ float4 g_boxes[BATCH * NSEL];
__device__ float  g_scoresT[BATCH * NCLS * NSEL];   // [b][c][s]
__device__ float  g_selscore[BATCH * NCLS * KTOP];
__device__ int    g_selidx[BATCH * NCLS * KTOP];

__device__ __forceinline__ unsigned f2u(float f) {
    unsigned u = __float_as_uint(f);
    return (u & 0x80000000u) ? ~u : (u | 0x80000000u);
}
__device__ __forceinline__ unsigned long long umax64(unsigned long long a, unsigned long long b) {
    return a > b ? a : b;
}

// ---------------- K1: max class logit per anchor (levels 0,1) ---------------
__global__ void k_maxlogit(const float* __restrict__ cls0, const float* __restrict__ cls1) {
    int gid = blockIdx.x * blockDim.x + threadIdx.x;
    const int n0 = BATCH * 6400;
    if (gid < n0) {
        const float* p = cls0 + (size_t)gid * NCLS;
        float m = p[0];
        #pragma unroll
        for (int i = 1; i < NCLS; i++) m = fmaxf(m, p[i]);
        g_ml0[gid] = m;
    } else {
        int g1 = gid - n0;
        if (g1 < BATCH * 1600) {
            const float* p = cls1 + (size_t)g1 * NCLS;
            float m = p[0];
            #pragma unroll
            for (int i = 1; i < NCLS; i++) m = fmaxf(m, p[i]);
            g_ml1[g1] = m;
        }
    }
}

// ---------------- K2: radix-select top-1000 per (batch, level) --------------
__global__ void __launch_bounds__(256) k_select() {
    __shared__ unsigned su[6400];
    __shared__ int sred[8];
    __shared__ int sb;
    __shared__ int c1, c2;
    int b = blockIdx.x >> 1, l = blockIdx.x & 1;
    int n = l ? 1600 : 6400;
    const float* src = l ? (g_ml1 + b * 1600) : (g_ml0 + b * 6400);
    int t = threadIdx.x;
    for (int i = t; i < n; i += 256) su[i] = f2u(src[i]);
    if (t == 0) { c1 = 0; c2 = 0; }
    __syncthreads();

    unsigned v = 0;
    for (int bit = 31; bit >= 0; --bit) {
        unsigned cand = v | (1u << bit);
        int cnt = 0;
        for (int i = t; i < n; i += 256) cnt += (su[i] >= cand);
        #pragma unroll
        for (int o = 16; o; o >>= 1) cnt += __shfl_down_sync(0xffffffffu, cnt, o);
        if ((t & 31) == 0) sred[t >> 5] = cnt;
        __syncthreads();
        if (t == 0) { int s = 0; for (int w = 0; w < 8; w++) s += sred[w]; sb = s; }
        __syncthreads();
        if (sb >= NPRE) v = cand;
    }
    // strictly greater count
    {
        int cnt = 0;
        for (int i = t; i < n; i += 256) cnt += (su[i] > v);
        #pragma unroll
        for (int o = 16; o; o >>= 1) cnt += __shfl_down_sync(0xffffffffu, cnt, o);
        if ((t & 31) == 0) sred[t >> 5] = cnt;
        __syncthreads();
        if (t == 0) { int s = 0; for (int w = 0; w < 8; w++) s += sred[w]; sb = s; }
        __syncthreads();
    }
    int G = sb;
    int* out = g_sel + (b * 2 + l) * NPRE;
    for (int i = t; i < n; i += 256)
        if (su[i] > v) { int p = atomicAdd(&c1, 1); out[p] = i; }
    __syncthreads();
    for (int i = t; i < n; i += 256)
        if (su[i] == v) { int p = atomicAdd(&c2, 1); if (G + p < NPRE) out[G + p] = i; }
}

// ---------------- K3: gather survivors, compute scores + DFL boxes ----------
__global__ void k_gather(const float* __restrict__ cls0, const float* __restrict__ cls1,
                         const float* __restrict__ cls2,
                         const float* __restrict__ bb0, const float* __restrict__ bb1,
                         const float* __restrict__ bb2) {
    int gid = blockIdx.x * blockDim.x + threadIdx.x;
    if (gid >= BATCH * NSEL) return;
    int b = gid / NSEL, s = gid % NSEL;
    const float* cls; const float* bb; int anchor; int w; float stride;
    if (s < 1000) {
        anchor = g_sel[(b * 2 + 0) * NPRE + s]; w = 80; stride = 8.f;
        cls = cls0 + ((size_t)b * 6400 + anchor) * NCLS;
        bb  = bb0 + ((size_t)b * 6400 + anchor) * 32;
    } else if (s < 2000) {
        anchor = g_sel[(b * 2 + 1) * NPRE + (s - 1000)]; w = 40; stride = 16.f;
        cls = cls1 + ((size_t)b * 1600 + anchor) * NCLS;
        bb  = bb1 + ((size_t)b * 1600 + anchor) * 32;
    } else {
        anchor = s - 2000; w = 20; stride = 32.f;
        cls = cls2 + ((size_t)b * 400 + anchor) * NCLS;
        bb  = bb2 + ((size_t)b * 400 + anchor) * 32;
    }
    float py = ((float)(anchor / w) + 0.5f) * stride;
    float px = ((float)(anchor % w) + 0.5f) * stride;
    float d[4];
    #pragma unroll
    for (int g = 0; g < 4; g++) {
        float x[8]; float m = -INFINITY;
        #pragma unroll
        for (int k = 0; k < 8; k++) { x[k] = bb[g * 8 + k]; m = fmaxf(m, x[k]); }
        float den = 0.f, num = 0.f;
        #pragma unroll
        for (int k = 0; k < 8; k++) { float e = expf(x[k] - m); den += e; num += e * (float)k; }
        d[g] = num / den * stride;
    }
    float y1 = fminf(fmaxf(py - d[0], 0.f), 640.f);
    float x1 = fminf(fmaxf(px - d[1], 0.f), 640.f);
    float y2 = fminf(fmaxf(py + d[2], 0.f), 640.f);
    float x2 = fminf(fmaxf(px + d[3], 0.f), 640.f);
    g_boxes[b * NSEL + s] = make_float4(y1, x1, y2, x2);
    #pragma unroll
    for (int c = 0; c < NCLS; c++) {
        float sc = 1.f / (1.f + expf(-cls[c]));
        g_scoresT[((size_t)b * NCLS + c) * NSEL + s] = sc;
    }
}

// ---------------- K4: greedy NMS, one block per (batch, class) --------------
// Keys live in registers pre-packed (score-bits || 2999-idx); suppression
// clears the hi word. One barrier per iteration (double-buffered wmax).
__global__ void __launch_bounds__(256) k_nms() {
    const int TPB = 256;
    const int ITEMS = 10;  // 10*256 = 2560 >= 2400
    int b = blockIdx.x / NCLS, c = blockIdx.x % NCLS;
    int t = threadIdx.x;
    const float*  scores = g_scoresT + ((size_t)b * NCLS + c) * NSEL;
    const float4* boxes  = g_boxes + b * NSEL;

    float y1[ITEMS], x1[ITEMS], y2[ITEMS], x2[ITEMS], ar[ITEMS];
    unsigned long long key[ITEMS];
    #pragma unroll
    for (int j = 0; j < ITEMS; j++) {
        int idx = j * TPB + t;
        if (idx < NSEL) {
            float4 v = boxes[idx];
            y1[j] = v.x; x1[j] = v.y; y2[j] = v.z; x2[j] = v.w;
            ar[j] = (v.z - v.x) * (v.w - v.y);
            key[j] = ((unsigned long long)f2u(scores[idx]) << 32)
                   | (unsigned)(2999 - idx);
        } else {
            y1[j] = x1[j] = y2[j] = x2[j] = 0.f; ar[j] = 0.f;
            key[j] = (unsigned long long)(unsigned)(2999 - idx);  // hi = 0: never wins vs real
        }
    }
    __shared__ unsigned long long wmax[2][8];
    float* selS = g_selscore + ((size_t)b * NCLS + c) * KTOP;
    int*   selI = g_selidx + ((size_t)b * NCLS + c) * KTOP;

    int p = 0;
    #pragma unroll 1
    for (int it = 0; it < KTOP; ++it) {
        // local max (tree)
        unsigned long long best = key[0];
        #pragma unroll
        for (int j = 1; j < ITEMS; j++) best = umax64(best, key[j]);
        // warp butterfly reduce (64-bit)
        #pragma unroll
        for (int o = 16; o; o >>= 1)
            best = umax64(best, __shfl_xor_sync(0xffffffffu, best, o));
        if ((t & 31) == 0) wmax[p][t >> 5] = best;
        __syncthreads();
        unsigned long long bk = wmax[p][0];
        #pragma unroll
        for (int w2 = 1; w2 < 8; w2++) bk = umax64(bk, wmax[p][w2]);
        p ^= 1;

        unsigned hi = (unsigned)(bk >> 32);
        if (hi == 0u) {
            // all remaining items are suppressed: reference picks idx 0 / -inf forever
            for (int r = it + t; r < KTOP; r += TPB) { selS[r] = -INFINITY; selI[r] = 0; }
            break;
        }
        int bidx = 2999 - (int)(unsigned)bk;
        if (t == (bidx & (TPB - 1))) {
            // owner lane: record selection (decode score bits exactly)
            selS[it] = __uint_as_float((hi & 0x80000000u) ? (hi ^ 0x80000000u) : ~hi);
            selI[it] = bidx;
        }
        // broadcast fetch of selected box (L1-resident, all threads same address)
        float4 bbx = __ldg(&boxes[bidx]);
        float a1 = (bbx.z - bbx.x) * (bbx.w - bbx.y);
        int tdiff = bidx - t;
        #pragma unroll
        for (int j = 0; j < ITEMS; j++) {
            float yy1 = fmaxf(bbx.x, y1[j]);
            float xx1 = fmaxf(bbx.y, x1[j]);
            float yy2 = fminf(bbx.z, y2[j]);
            float xx2 = fminf(bbx.w, x2[j]);
            float inter = fmaxf(yy2 - yy1, 0.f) * fmaxf(xx2 - xx1, 0.f);
            // EXACT same expression/order as reference (IEEE div, same assoc)
            float iou = inter / (a1 + ar[j] - inter + 1e-9f);
            bool kill = (iou > 0.5f) || (tdiff == j * TPB);
            if (kill) key[j] = (unsigned long long)(unsigned)key[j];  // clear hi word
        }
    }
}

// ---------------- K5: per-batch bitonic top-100 + masking -------------------
__global__ void __launch_bounds__(1024) k_final(float* __restrict__ out) {
    __shared__ unsigned long long keys[2048];
    int b = blockIdx.x, t = threadIdx.x;
    for (int i = t; i < 2048; i += 1024) {
        unsigned long long key = 0ull;
        if (i < NCLS * KTOP) {
            float s = g_selscore[(size_t)b * NCLS * KTOP + i];
            float fs = isfinite(s) ? s : -1.0f;
            // descending score, then ascending flat index (class-major), like lax.top_k
            key = ((unsigned long long)f2u(fs) << 32) | (unsigned)(0xFFFFFFFFu - (unsigned)i);
        }
        keys[i] = key;
    }
    __syncthreads();
    for (int k = 2; k <= 2048; k <<= 1) {
        for (int j = k >> 1; j > 0; j >>= 1) {
            for (int i = t; i < 2048; i += 1024) {
                int ixj = i ^ j;
                if (ixj > i) {
                    bool desc = (i & k) == 0;
                    unsigned long long a = keys[i], bb2 = keys[ixj];
                    bool sw = desc ? (a < bb2) : (a > bb2);
                    if (sw) { keys[i] = bb2; keys[ixj] = a; }
                }
            }
            __syncthreads();
        }
    }
    if (t < KTOP) {
        unsigned long long key = keys[t];
        unsigned low = (unsigned)(key & 0xFFFFFFFFull);
        unsigned i = 0xFFFFFFFFu - low;
        float* o = out + ((size_t)b * KTOP + t) * 6;
        float vals[6] = {0.f, 0.f, 0.f, 0.f, 0.f, 0.f};
        if (i < (unsigned)(NCLS * KTOP)) {
            int c = (int)i / KTOP, kk = (int)i % KTOP;
            float s = g_selscore[((size_t)b * NCLS + c) * KTOP + kk];
            if (isfinite(s) && s > 0.3f) {   // ok-mask and score-mask combined
                int idx = g_selidx[((size_t)b * NCLS + c) * KTOP + kk];
                float4 bx = g_boxes[b * NSEL + idx];
                vals[0] = bx.x; vals[1] = bx.y; vals[2] = bx.z; vals[3] = bx.w;
                vals[4] = s; vals[5] = (float)c;
            }
        }
        #pragma unroll
        for (int q = 0; q < 6; q++) o[q] = vals[q];
    }
}

// ---------------- launch -----------------------------------------------------
extern "C" void kernel_launch(void* const* d_in, const int* in_sizes, int n_in,
                              void* d_out, int out_size) {
    const float *cls0 = 0, *cls1 = 0, *cls2 = 0, *bb0 = 0, *bb1 = 0, *bb2 = 0;
    for (int i = 0; i < n_in; i++) {
        const float* p = (const float*)d_in[i];
        switch (in_sizes[i]) {
            case 2048000: cls0 = p; break;  // 16*6400*20
            case 3276800: bb0  = p; break;  // 16*6400*32
            case 512000:  cls1 = p; break;  // 16*1600*20
            case 819200:  bb1  = p; break;  // 16*1600*32
            case 128000:  cls2 = p; break;  // 16*400*20
            case 204800:  bb2  = p; break;  // 16*400*32
            default: break;                 // origin_shapes (unused by reference)
        }
    }
    k_maxlogit<<<(BATCH * 8000 + 255) / 256, 256>>>(cls0, cls1);
    k_select<<<32, 256>>>();
    k_gather<<<(BATCH * NSEL + 255) / 256, 256>>>(cls0, cls1, cls2, bb0, bb1, bb2);
    k_nms<<<BATCH * NCLS, 256>>>();
    k_final<<<BATCH, 1024>>>((float*)d_out);
}

// round 3
// speedup vs baseline: 1.8803x; 1.3826x over previous
#include <cuda_runtime.h>
#include <math.h>

#define BATCH 16
#define NCLS  20
#define NSEL  2400
#define KTOP  100
#define NPRE  1000
#define SORTN 4096

// ---------------- scratch (device globals; no allocations allowed) ----------
__device__ int    g_sel[BATCH * 2 * NPRE];
__device__ float4 g_boxes[BATCH * NSEL];
__device__ float  g_scoresT[BATCH * NCLS * NSEL];   // [b][c][s]
__device__ float  g_selscore[BATCH * NCLS * KTOP];
__device__ int    g_selidx[BATCH * NCLS * KTOP];

__device__ __forceinline__ unsigned f2u(float f) {
    unsigned u = __float_as_uint(f);
    return (u & 0x80000000u) ? ~u : (u | 0x80000000u);
}
__device__ __forceinline__ unsigned long long umax64(unsigned long long a, unsigned long long b) {
    return a > b ? a : b;
}

// ---------- K1: fused max-logit + radix-select top-1000 per (batch, level) --
__global__ void __launch_bounds__(256) k_select(const float* __restrict__ cls0,
                                                const float* __restrict__ cls1) {
    __shared__ unsigned su[6400];
    __shared__ int sred[8];
    __shared__ int sb;
    __shared__ int c1, c2;
    int b = blockIdx.x >> 1, l = blockIdx.x & 1;
    int n = l ? 1600 : 6400;
    const float* src = l ? (cls1 + (size_t)b * 1600 * NCLS)
                         : (cls0 + (size_t)b * 6400 * NCLS);
    int t = threadIdx.x;
    for (int i = t; i < n; i += 256) {
        const float4* p = (const float4*)(src + (size_t)i * NCLS);
        float4 v0 = p[0], v1 = p[1], v2 = p[2], v3 = p[3], v4 = p[4];
        float m = fmaxf(fmaxf(fmaxf(v0.x, v0.y), fmaxf(v0.z, v0.w)),
                        fmaxf(fmaxf(v1.x, v1.y), fmaxf(v1.z, v1.w)));
        m = fmaxf(m, fmaxf(fmaxf(v2.x, v2.y), fmaxf(v2.z, v2.w)));
        m = fmaxf(m, fmaxf(fmaxf(v3.x, v3.y), fmaxf(v3.z, v3.w)));
        m = fmaxf(m, fmaxf(fmaxf(v4.x, v4.y), fmaxf(v4.z, v4.w)));
        su[i] = f2u(m);
    }
    if (t == 0) { c1 = 0; c2 = 0; }
    __syncthreads();

    unsigned v = 0;
    for (int bit = 31; bit >= 0; --bit) {
        unsigned cand = v | (1u << bit);
        int cnt = 0;
        for (int i = t; i < n; i += 256) cnt += (su[i] >= cand);
        #pragma unroll
        for (int o = 16; o; o >>= 1) cnt += __shfl_down_sync(0xffffffffu, cnt, o);
        if ((t & 31) == 0) sred[t >> 5] = cnt;
        __syncthreads();
        if (t == 0) { int s = 0; for (int w = 0; w < 8; w++) s += sred[w]; sb = s; }
        __syncthreads();
        if (sb >= NPRE) v = cand;
    }
    {
        int cnt = 0;
        for (int i = t; i < n; i += 256) cnt += (su[i] > v);
        #pragma unroll
        for (int o = 16; o; o >>= 1) cnt += __shfl_down_sync(0xffffffffu, cnt, o);
        if ((t & 31) == 0) sred[t >> 5] = cnt;
        __syncthreads();
        if (t == 0) { int s = 0; for (int w = 0; w < 8; w++) s += sred[w]; sb = s; }
        __syncthreads();
    }
    int G = sb;
    int* out = g_sel + (b * 2 + l) * NPRE;
    for (int i = t; i < n; i += 256)
        if (su[i] > v) { int p = atomicAdd(&c1, 1); out[p] = i; }
    __syncthreads();
    for (int i = t; i < n; i += 256)
        if (su[i] == v) { int p = atomicAdd(&c2, 1); if (G + p < NPRE) out[G + p] = i; }
}

// ---------------- K2: gather survivors, compute scores + DFL boxes ----------
__global__ void k_gather(const float* __restrict__ cls0, const float* __restrict__ cls1,
                         const float* __restrict__ cls2,
                         const float* __restrict__ bb0, const float* __restrict__ bb1,
                         const float* __restrict__ bb2) {
    int gid = blockIdx.x * blockDim.x + threadIdx.x;
    if (gid >= BATCH * NSEL) return;
    int b = gid / NSEL, s = gid % NSEL;
    const float* cls; const float* bb; int anchor; int w; float stride;
    if (s < 1000) {
        anchor = g_sel[(b * 2 + 0) * NPRE + s]; w = 80; stride = 8.f;
        cls = cls0 + ((size_t)b * 6400 + anchor) * NCLS;
        bb  = bb0 + ((size_t)b * 6400 + anchor) * 32;
    } else if (s < 2000) {
        anchor = g_sel[(b * 2 + 1) * NPRE + (s - 1000)]; w = 40; stride = 16.f;
        cls = cls1 + ((size_t)b * 1600 + anchor) * NCLS;
        bb  = bb1 + ((size_t)b * 1600 + anchor) * 32;
    } else {
        anchor = s - 2000; w = 20; stride = 32.f;
        cls = cls2 + ((size_t)b * 400 + anchor) * NCLS;
        bb  = bb2 + ((size_t)b * 400 + anchor) * 32;
    }
    float py = ((float)(anchor / w) + 0.5f) * stride;
    float px = ((float)(anchor % w) + 0.5f) * stride;
    float d[4];
    #pragma unroll
    for (int g = 0; g < 4; g++) {
        float x[8]; float m = -INFINITY;
        #pragma unroll
        for (int k = 0; k < 8; k++) { x[k] = bb[g * 8 + k]; m = fmaxf(m, x[k]); }
        float den = 0.f, num = 0.f;
        #pragma unroll
        for (int k = 0; k < 8; k++) { float e = expf(x[k] - m); den += e; num += e * (float)k; }
        d[g] = num / den * stride;
    }
    float y1 = fminf(fmaxf(py - d[0], 0.f), 640.f);
    float x1 = fminf(fmaxf(px - d[1], 0.f), 640.f);
    float y2 = fminf(fmaxf(py + d[2], 0.f), 640.f);
    float x2 = fminf(fmaxf(px + d[3], 0.f), 640.f);
    g_boxes[b * NSEL + s] = make_float4(y1, x1, y2, x2);
    #pragma unroll
    for (int c = 0; c < NCLS; c++) {
        float sc = 1.f / (1.f + expf(-cls[c]));
        g_scoresT[((size_t)b * NCLS + c) * NSEL + s] = sc;
    }
}

// ---------------- K3: sorted-scan greedy NMS, one block per (batch, class) --
// Greedy NMS == scan candidates in descending score order; accept iff not
// suppressed (IoU > 0.5) by any already-accepted box. Bitonic sort (parallel)
// + warp-0 scan with <=100-wide parallel IoU checks.
__global__ void __launch_bounds__(256) k_nms() {
    __shared__ unsigned long long skey[SORTN];
    __shared__ float sely1[128], selx1[128], sely2[128], selx2[128], selar[128];
    int b = blockIdx.x / NCLS, c = blockIdx.x % NCLS;
    int t = threadIdx.x;
    const float*  scores = g_scoresT + ((size_t)b * NCLS + c) * NSEL;
    const float4* boxes  = g_boxes + b * NSEL;

    // pack keys: score-sortable-bits || (SORTN-1-idx) so equal scores order by
    // ascending original index (matches jnp.argmax first-max tie-break)
    for (int i = t; i < SORTN; i += 256) {
        unsigned long long k = (unsigned long long)(unsigned)(SORTN - 1 - i);
        if (i < NSEL) k |= ((unsigned long long)f2u(scores[i]) << 32);
        skey[i] = k;
    }
    __syncthreads();
    // bitonic sort, descending at the front
    for (int k = 2; k <= SORTN; k <<= 1) {
        for (int j = k >> 1; j > 0; j >>= 1) {
            for (int m = t; m < SORTN; m += 256) {
                int ixj = m ^ j;
                if (ixj > m) {
                    bool desc = (m & k) == 0;
                    unsigned long long a = skey[m], b2 = skey[ixj];
                    bool sw = desc ? (a < b2) : (a > b2);
                    if (sw) { skey[m] = b2; skey[ixj] = a; }
                }
            }
            __syncthreads();
        }
    }

    float* selS = g_selscore + ((size_t)b * NCLS + c) * KTOP;
    int*   selI = g_selidx + ((size_t)b * NCLS + c) * KTOP;
    if (t < 32) {
        int ns = 0;
        for (int pos = 0; pos < NSEL && ns < KTOP; ++pos) {
            unsigned long long key = skey[pos];
            int idx = (SORTN - 1) - (int)(unsigned)(key & 0xffffffffull);
            float4 bx = __ldg(&boxes[idx]);          // broadcast, L1-hot
            float a2 = (bx.z - bx.x) * (bx.w - bx.y);
            bool sup = false;
            for (int base = 0; base < ns; base += 32) {
                int si = base + t;
                if (si < ns) {
                    float yy1 = fmaxf(sely1[si], bx.x);
                    float xx1 = fmaxf(selx1[si], bx.y);
                    float yy2 = fminf(sely2[si], bx.z);
                    float xx2 = fminf(selx2[si], bx.w);
                    float inter = fmaxf(yy2 - yy1, 0.f) * fmaxf(xx2 - xx1, 0.f);
                    // exact reference expression order: a1 + a2 - inter + eps
                    float iou = inter / (selar[si] + a2 - inter + 1e-9f);
                    sup |= (iou > 0.5f);
                }
            }
            if (!__any_sync(0xffffffffu, sup)) {
                if (t == 0) {
                    sely1[ns] = bx.x; selx1[ns] = bx.y;
                    sely2[ns] = bx.z; selx2[ns] = bx.w; selar[ns] = a2;
                    unsigned hi = (unsigned)(key >> 32);
                    selS[ns] = __uint_as_float((hi & 0x80000000u) ? (hi ^ 0x80000000u) : ~hi);
                    selI[ns] = idx;
                }
                ns++;
                __syncwarp();
            }
        }
        // fewer than KTOP survivors: reference keeps argmax of all -inf
        for (int r = ns + t; r < KTOP; r += 32) { selS[r] = -INFINITY; selI[r] = 0; }
    }
}

// ---------------- K4: per-batch bitonic top-100 + masking -------------------
__global__ void __launch_bounds__(1024) k_final(float* __restrict__ out) {
    __shared__ unsigned long long keys[2048];
    int b = blockIdx.x, t = threadIdx.x;
    for (int i = t; i < 2048; i += 1024) {
        unsigned long long key = 0ull;
        if (i < NCLS * KTOP) {
            float s = g_selscore[(size_t)b * NCLS * KTOP + i];
            float fs = isfinite(s) ? s : -1.0f;
            key = ((unsigned long long)f2u(fs) << 32) | (unsigned)(0xFFFFFFFFu - (unsigned)i);
        }
        keys[i] = key;
    }
    __syncthreads();
    for (int k = 2; k <= 2048; k <<= 1) {
        for (int j = k >> 1; j > 0; j >>= 1) {
            for (int i = t; i < 2048; i += 1024) {
                int ixj = i ^ j;
                if (ixj > i) {
                    bool desc = (i & k) == 0;
                    unsigned long long a = keys[i], bb2 = keys[ixj];
                    bool sw = desc ? (a < bb2) : (a > bb2);
                    if (sw) { keys[i] = bb2; keys[ixj] = a; }
                }
            }
            __syncthreads();
        }
    }
    if (t < KTOP) {
        unsigned long long key = keys[t];
        unsigned low = (unsigned)(key & 0xFFFFFFFFull);
        unsigned i = 0xFFFFFFFFu - low;
        float* o = out + ((size_t)b * KTOP + t) * 6;
        float vals[6] = {0.f, 0.f, 0.f, 0.f, 0.f, 0.f};
        if (i < (unsigned)(NCLS * KTOP)) {
            int c = (int)i / KTOP, kk = (int)i % KTOP;
            float s = g_selscore[((size_t)b * NCLS + c) * KTOP + kk];
            if (isfinite(s) && s > 0.3f) {
                int idx = g_selidx[((size_t)b * NCLS + c) * KTOP + kk];
                float4 bx = g_boxes[b * NSEL + idx];
                vals[0] = bx.x; vals[1] = bx.y; vals[2] = bx.z; vals[3] = bx.w;
                vals[4] = s; vals[5] = (float)c;
            }
        }
        #pragma unroll
        for (int q = 0; q < 6; q++) o[q] = vals[q];
    }
}

// ---------------- launch -----------------------------------------------------
extern "C" void kernel_launch(void* const* d_in, const int* in_sizes, int n_in,
                              void* d_out, int out_size) {
    const float *cls0 = 0, *cls1 = 0, *cls2 = 0, *bb0 = 0, *bb1 = 0, *bb2 = 0;
    for (int i = 0; i < n_in; i++) {
        const float* p = (const float*)d_in[i];
        switch (in_sizes[i]) {
            case 2048000: cls0 = p; break;  // 16*6400*20
            case 3276800: bb0  = p; break;  // 16*6400*32
            case 512000:  cls1 = p; break;  // 16*1600*20
            case 819200:  bb1  = p; break;  // 16*1600*32
            case 128000:  cls2 = p; break;  // 16*400*20
            case 204800:  bb2  = p; break;  // 16*400*32
            default: break;                 // origin_shapes (unused by reference)
        }
    }
    k_select<<<32, 256>>>(cls0, cls1);
    k_gather<<<(BATCH * NSEL + 255) / 256, 256>>>(cls0, cls1, cls2, bb0, bb1, bb2);
    k_nms<<<BATCH * NCLS, 256>>>();
    k_final<<<BATCH, 1024>>>((float*)d_out);
}

// round 4
// speedup vs baseline: 3.2812x; 1.7450x over previous
#include <cuda_runtime.h>
#include <math.h>

#define BATCH 16
#define NCLS  20
#define NSEL  2400
#define KTOP  100
#define NPRE  1000
#define CHUNK 256     // radix-select rank per NMS chunk
#define CHCAP 448     // capacity incl. boundary ties
#define CHSORT 512    // pow2 sort width

// ---------------- scratch (device globals; no allocations allowed) ----------
__device__ float  g_ml0[BATCH * 6400];
__device__ float  g_ml1[BATCH * 1600];
__device__ int    g_sel[BATCH * 2 * NPRE];
__device__ float4 g_boxes[BATCH * NSEL];
__device__ float  g_scoresT[BATCH * NCLS * NSEL];   // [b][c][s]
__device__ float  g_selscore[BATCH * NCLS * KTOP];
__device__ int    g_selidx[BATCH * NCLS * KTOP];

__device__ __forceinline__ unsigned f2u(float f) {
    unsigned u = __float_as_uint(f);
    return (u & 0x80000000u) ? ~u : (u | 0x80000000u);
}
__device__ __forceinline__ float u2f(unsigned h) {
    return __uint_as_float((h & 0x80000000u) ? (h ^ 0x80000000u) : ~h);
}

// ---------------- K1: max class logit per anchor (levels 0,1) ---------------
__global__ void k_maxlogit(const float* __restrict__ cls0, const float* __restrict__ cls1) {
    int gid = blockIdx.x * blockDim.x + threadIdx.x;
    const int n0 = BATCH * 6400;
    const float* p; float* o;
    if (gid < n0) { p = cls0 + (size_t)gid * NCLS; o = g_ml0 + gid; }
    else {
        int g1 = gid - n0;
        if (g1 >= BATCH * 1600) return;
        p = cls1 + (size_t)g1 * NCLS; o = g_ml1 + g1;
    }
    const float4* q = (const float4*)p;
    float4 v0 = q[0], v1 = q[1], v2 = q[2], v3 = q[3], v4 = q[4];
    float m = fmaxf(fmaxf(fmaxf(v0.x, v0.y), fmaxf(v0.z, v0.w)),
                    fmaxf(fmaxf(v1.x, v1.y), fmaxf(v1.z, v1.w)));
    m = fmaxf(m, fmaxf(fmaxf(v2.x, v2.y), fmaxf(v2.z, v2.w)));
    m = fmaxf(m, fmaxf(fmaxf(v3.x, v3.y), fmaxf(v3.z, v3.w)));
    m = fmaxf(m, fmaxf(fmaxf(v4.x, v4.y), fmaxf(v4.z, v4.w)));
    *o = m;
}

// ---------------- K2: radix-select top-1000 per (batch, level) --------------
__global__ void __launch_bounds__(256) k_select() {
    __shared__ unsigned su[6400];
    __shared__ int sred[8];
    __shared__ int sb;
    __shared__ int c1, c2;
    int b = blockIdx.x >> 1, l = blockIdx.x & 1;
    int n = l ? 1600 : 6400;
    const float* src = l ? (g_ml1 + b * 1600) : (g_ml0 + b * 6400);
    int t = threadIdx.x;
    for (int i = t; i < n; i += 256) su[i] = f2u(src[i]);
    if (t == 0) { c1 = 0; c2 = 0; }
    __syncthreads();

    unsigned v = 0;
    for (int bit = 31; bit >= 0; --bit) {
        unsigned cand = v | (1u << bit);
        int cnt = 0;
        for (int i = t; i < n; i += 256) cnt += (su[i] >= cand);
        #pragma unroll
        for (int o = 16; o; o >>= 1) cnt += __shfl_down_sync(0xffffffffu, cnt, o);
        if ((t & 31) == 0) sred[t >> 5] = cnt;
        __syncthreads();
        if (t == 0) { int s = 0; for (int w = 0; w < 8; w++) s += sred[w]; sb = s; }
        __syncthreads();
        if (sb >= NPRE) v = cand;
    }
    {
        int cnt = 0;
        for (int i = t; i < n; i += 256) cnt += (su[i] > v);
        #pragma unroll
        for (int o = 16; o; o >>= 1) cnt += __shfl_down_sync(0xffffffffu, cnt, o);
        if ((t & 31) == 0) sred[t >> 5] = cnt;
        __syncthreads();
        if (t == 0) { int s = 0; for (int w = 0; w < 8; w++) s += sred[w]; sb = s; }
        __syncthreads();
    }
    int G = sb;
    int* out = g_sel + (b * 2 + l) * NPRE;
    for (int i = t; i < n; i += 256)
        if (su[i] > v) { int p = atomicAdd(&c1, 1); out[p] = i; }
    __syncthreads();
    for (int i = t; i < n; i += 256)
        if (su[i] == v) { int p = atomicAdd(&c2, 1); if (G + p < NPRE) out[G + p] = i; }
}

// ---------------- K3: gather survivors, compute scores + DFL boxes ----------
__global__ void k_gather(const float* __restrict__ cls0, const float* __restrict__ cls1,
                         const float* __restrict__ cls2,
                         const float* __restrict__ bb0, const float* __restrict__ bb1,
                         const float* __restrict__ bb2) {
    int gid = blockIdx.x * blockDim.x + threadIdx.x;
    if (gid >= BATCH * NSEL) return;
    int b = gid / NSEL, s = gid % NSEL;
    const float* cls; const float* bb; int anchor; int w; float stride;
    if (s < 1000) {
        anchor = g_sel[(b * 2 + 0) * NPRE + s]; w = 80; stride = 8.f;
        cls = cls0 + ((size_t)b * 6400 + anchor) * NCLS;
        bb  = bb0 + ((size_t)b * 6400 + anchor) * 32;
    } else if (s < 2000) {
        anchor = g_sel[(b * 2 + 1) * NPRE + (s - 1000)]; w = 40; stride = 16.f;
        cls = cls1 + ((size_t)b * 1600 + anchor) * NCLS;
        bb  = bb1 + ((size_t)b * 1600 + anchor) * 32;
    } else {
        anchor = s - 2000; w = 20; stride = 32.f;
        cls = cls2 + ((size_t)b * 400 + anchor) * NCLS;
        bb  = bb2 + ((size_t)b * 400 + anchor) * 32;
    }
    float py = ((float)(anchor / w) + 0.5f) * stride;
    float px = ((float)(anchor % w) + 0.5f) * stride;
    float d[4];
    #pragma unroll
    for (int g = 0; g < 4; g++) {
        float x[8]; float m = -INFINITY;
        #pragma unroll
        for (int k = 0; k < 8; k++) { x[k] = bb[g * 8 + k]; m = fmaxf(m, x[k]); }
        float den = 0.f, num = 0.f;
        #pragma unroll
        for (int k = 0; k < 8; k++) { float e = expf(x[k] - m); den += e; num += e * (float)k; }
        d[g] = num / den * stride;
    }
    float y1 = fminf(fmaxf(py - d[0], 0.f), 640.f);
    float x1 = fminf(fmaxf(px - d[1], 0.f), 640.f);
    float y2 = fminf(fmaxf(py + d[2], 0.f), 640.f);
    float x2 = fminf(fmaxf(px + d[3], 0.f), 640.f);
    g_boxes[b * NSEL + s] = make_float4(y1, x1, y2, x2);
    #pragma unroll
    for (int c = 0; c < NCLS; c++) {
        float sc = 1.f / (1.f + expf(-cls[c]));
        g_scoresT[((size_t)b * NCLS + c) * NSEL + s] = sc;
    }
}

// ---------------- K4: chunked radix-select + sorted-scan NMS ----------------
// Greedy NMS == scan in descending score order, accept iff not suppressed by
// an already-accepted box. Process candidates in chunks: radix-select the
// top-CHUNK (incl. all boundary ties => exact prefix), sort the small chunk,
// scan. Loop (rare) with upper bound = previous pivot.
__global__ void __launch_bounds__(256) k_nms() {
    __shared__ unsigned su[NSEL];
    __shared__ int tmpidx[CHCAP];
    __shared__ unsigned long long skey[CHSORT];
    __shared__ float cby1[CHCAP], cbx1[CHCAP], cby2[CHCAP], cbx2[CHCAP], cbar[CHCAP];
    __shared__ float ay1[KTOP], ax1[KTOP], ay2[KTOP], ax2[KTOP], aar[KTOP];
    __shared__ int sred[8];
    __shared__ int sb, sL, s_ns;

    int b = blockIdx.x / NCLS, c = blockIdx.x % NCLS;
    int t = threadIdx.x;
    const float*  scores = g_scoresT + ((size_t)b * NCLS + c) * NSEL;
    const float4* boxes  = g_boxes + b * NSEL;
    float* selS = g_selscore + ((size_t)b * NCLS + c) * KTOP;
    int*   selI = g_selidx + ((size_t)b * NCLS + c) * KTOP;

    for (int i = t; i < NSEL; i += 256) su[i] = f2u(scores[i]);
    if (t == 0) s_ns = 0;
    __syncthreads();

    unsigned U = 0xFFFFFFFFu;   // exclusive upper bound on remaining keys
    int ns = 0, processed = 0;

    while (ns < KTOP && processed < NSEL) {
        int M = NSEL - processed; if (M > CHUNK) M = CHUNK;
        // -------- radix-select pivot = rank-M key among {key < U} ----------
        unsigned v = 0;
        for (int bit = 31; bit >= 0; --bit) {
            unsigned cand = v | (1u << bit);
            int cnt = 0;
            for (int i = t; i < NSEL; i += 256) {
                unsigned k = su[i];
                cnt += (k < U && k >= cand);
            }
            #pragma unroll
            for (int o = 16; o; o >>= 1) cnt += __shfl_down_sync(0xffffffffu, cnt, o);
            if ((t & 31) == 0) sred[t >> 5] = cnt;
            __syncthreads();
            if (t == 0) { int s = 0; for (int w = 0; w < 8; w++) s += sred[w]; sb = s; }
            __syncthreads();
            if (sb >= M) v = cand;
        }
        unsigned pivot = v;
        // -------- compact all keys in [pivot, U) ---------------------------
        if (t == 0) sL = 0;
        __syncthreads();
        for (int i = t; i < NSEL; i += 256) {
            unsigned k = su[i];
            if (k < U && k >= pivot) {
                int p = atomicAdd(&sL, 1);
                if (p < CHCAP) tmpidx[p] = i;
            }
        }
        __syncthreads();
        int Ltrue = sL;
        int L = Ltrue < CHCAP ? Ltrue : CHCAP;
        // -------- build 64-bit keys, pad, bitonic sort desc ----------------
        for (int p = t; p < CHSORT; p += 256) {
            unsigned long long k = 0ull;
            if (p < L) {
                int i = tmpidx[p];
                k = ((unsigned long long)su[i] << 32) | (unsigned)(4095 - i);
            }
            skey[p] = k;
        }
        __syncthreads();
        for (int k = 2; k <= CHSORT; k <<= 1) {
            for (int j = k >> 1; j > 0; j >>= 1) {
                for (int m = t; m < CHSORT; m += 256) {
                    int ixj = m ^ j;
                    if (ixj > m) {
                        bool desc = (m & k) == 0;
                        unsigned long long a = skey[m], b2 = skey[ixj];
                        bool sw = desc ? (a < b2) : (a > b2);
                        if (sw) { skey[m] = b2; skey[ixj] = a; }
                    }
                }
                __syncthreads();
            }
        }
        // -------- prefetch candidate boxes (sorted order) ------------------
        for (int p = t; p < L; p += 256) {
            int idx = 4095 - (int)(unsigned)(skey[p] & 0xffffffffull);
            float4 bx = boxes[idx];
            cby1[p] = bx.x; cbx1[p] = bx.y; cby2[p] = bx.z; cbx2[p] = bx.w;
            cbar[p] = (bx.z - bx.x) * (bx.w - bx.y);
        }
        __syncthreads();
        // -------- serial scan (warp 0) --------------------------------------
        if (t < 32) {
            int n2 = ns;
            for (int pos = 0; pos < L && n2 < KTOP; ++pos) {
                float by1 = cby1[pos], bx1 = cbx1[pos];
                float by2 = cby2[pos], bx2 = cbx2[pos], a2 = cbar[pos];
                bool sup = false;
                for (int base = 0; base < n2; base += 32) {
                    int si = base + t;
                    if (si < n2) {
                        float yy1 = fmaxf(ay1[si], by1);
                        float xx1 = fmaxf(ax1[si], bx1);
                        float yy2 = fminf(ay2[si], by2);
                        float xx2 = fminf(ax2[si], bx2);
                        float inter = fmaxf(yy2 - yy1, 0.f) * fmaxf(xx2 - xx1, 0.f);
                        float iou = inter / (aar[si] + a2 - inter + 1e-9f);
                        sup |= (iou > 0.5f);
                    }
                }
                if (!__any_sync(0xffffffffu, sup)) {
                    if (t == 0) {
                        ay1[n2] = by1; ax1[n2] = bx1; ay2[n2] = by2; ax2[n2] = bx2; aar[n2] = a2;
                        unsigned long long key = skey[pos];
                        selS[n2] = u2f((unsigned)(key >> 32));
                        selI[n2] = 4095 - (int)(unsigned)(key & 0xffffffffull);
                    }
                    n2++;
                    __syncwarp();
                }
            }
            if (t == 0) s_ns = n2;
        }
        __syncthreads();
        ns = s_ns;
        processed += Ltrue;
        U = pivot;
    }
    // fewer than KTOP survivors: reference yields argmax over all -inf
    for (int r = ns + t; r < KTOP; r += 256) { selS[r] = -INFINITY; selI[r] = 0; }
}

// ---------------- K5: per-batch radix top-100 + masking ---------------------
__global__ void __launch_bounds__(256) k_final(float* __restrict__ out) {
    __shared__ unsigned su2[NCLS * KTOP];
    __shared__ int tmpidx[256];
    __shared__ unsigned long long skey[256];
    __shared__ int sred[8];
    __shared__ int sb, sL;
    int b = blockIdx.x, t = threadIdx.x;
    const int N2 = NCLS * KTOP;   // 2000
    const float* sel = g_selscore + (size_t)b * N2;

    for (int i = t; i < N2; i += 256) {
        float s = sel[i];
        float fs = isfinite(s) ? s : -1.0f;
        su2[i] = f2u(fs);
    }
    if (t == 0) sL = 0;
    __syncthreads();

    unsigned v = 0;
    for (int bit = 31; bit >= 0; --bit) {
        unsigned cand = v | (1u << bit);
        int cnt = 0;
        for (int i = t; i < N2; i += 256) cnt += (su2[i] >= cand);
        #pragma unroll
        for (int o = 16; o; o >>= 1) cnt += __shfl_down_sync(0xffffffffu, cnt, o);
        if ((t & 31) == 0) sred[t >> 5] = cnt;
        __syncthreads();
        if (t == 0) { int s = 0; for (int w = 0; w < 8; w++) s += sred[w]; sb = s; }
        __syncthreads();
        if (sb >= KTOP) v = cand;
    }
    // compact all >= pivot (incl. ties; exact prefix of sorted order)
    for (int i = t; i < N2; i += 256)
        if (su2[i] >= v) { int p = atomicAdd(&sL, 1); if (p < 256) tmpidx[p] = i; }
    __syncthreads();
    int L = sL < 256 ? sL : 256;
    for (int p = t; p < 256; p += 256) {
        unsigned long long k = 0ull;
        if (p < L) {
            int i = tmpidx[p];
            k = ((unsigned long long)su2[i] << 32) | (unsigned)(4095 - i);
        }
        skey[p] = k;
    }
    __syncthreads();
    for (int k = 2; k <= 256; k <<= 1) {
        for (int j = k >> 1; j > 0; j >>= 1) {
            int ixj = t ^ j;
            if (ixj > t) {
                bool desc = (t & k) == 0;
                unsigned long long a = skey[t], b2 = skey[ixj];
                bool sw = desc ? (a < b2) : (a > b2);
                if (sw) { skey[t] = b2; skey[ixj] = a; }
            }
            __syncthreads();
        }
    }
    if (t < KTOP) {
        int i = 4095 - (int)(unsigned)(skey[t] & 0xffffffffull);
        float* o = out + ((size_t)b * KTOP + t) * 6;
        float vals[6] = {0.f, 0.f, 0.f, 0.f, 0.f, 0.f};
        if (t < L) {
            int c = i / KTOP, kk = i % KTOP;
            float s = g_selscore[((size_t)b * NCLS + c) * KTOP + kk];
            if (isfinite(s) && s > 0.3f) {
                int idx = g_selidx[((size_t)b * NCLS + c) * KTOP + kk];
                float4 bx = g_boxes[b * NSEL + idx];
                vals[0] = bx.x; vals[1] = bx.y; vals[2] = bx.z; vals[3] = bx.w;
                vals[4] = s; vals[5] = (float)c;
            }
        }
        #pragma unroll
        for (int q = 0; q < 6; q++) o[q] = vals[q];
    }
}

// ---------------- launch -----------------------------------------------------
extern "C" void kernel_launch(void* const* d_in, const int* in_sizes, int n_in,
                              void* d_out, int out_size) {
    const float *cls0 = 0, *cls1 = 0, *cls2 = 0, *bb0 = 0, *bb1 = 0, *bb2 = 0;
    for (int i = 0; i < n_in; i++) {
        const float* p = (const float*)d_in[i];
        switch (in_sizes[i]) {
            case 2048000: cls0 = p; break;  // 16*6400*20
            case 3276800: bb0  = p; break;  // 16*6400*32
            case 512000:  cls1 = p; break;  // 16*1600*20
            case 819200:  bb1  = p; break;  // 16*1600*32
            case 128000:  cls2 = p; break;  // 16*400*20
            case 204800:  bb2  = p; break;  // 16*400*32
            default: break;                 // origin_shapes (unused by reference)
        }
    }
    k_maxlogit<<<(BATCH * 8000 + 255) / 256, 256>>>(cls0, cls1);
    k_select<<<32, 256>>>();
    k_gather<<<(BATCH * NSEL + 255) / 256, 256>>>(cls0, cls1, cls2, bb0, bb1, bb2);
    k_nms<<<BATCH * NCLS, 256>>>();
    k_final<<<BATCH, 256>>>((float*)d_out);
}